// round 1
// baseline (speedup 1.0000x reference)
#include <cuda_runtime.h>

// ---------------------------------------------------------------------------
// CayleyNet: 2x CayleyConv (R=3, K=4 Jacobi) + TopKPooling(0.9) + mean pool + linear
// N=50000 nodes, E=800000 edges, H=64 channels, G=10 graphs (5000 nodes each)
// ---------------------------------------------------------------------------

#define NN    50000
#define EE    800000
#define HH    64
#define HC    32          // float4 lanes per node (2 complex channels each)
#define GG    10
#define NPG   5000
#define KKEEP 4500        // ceil(0.9 * 5000)

// ---------------- static device scratch (no allocations allowed) ----------
__device__ int g_cntR[NN];
__device__ int g_cntC[NN];
__device__ int g_rptr[NN + 1];
__device__ int g_cptr[NN + 1];
__device__ int g_adjR[EE];           // grouped by row: stores col (dst)
__device__ int g_adjC[EE];           // grouped by col: stores row (src)
__device__ float2 g_jw[NN];          // h * tmp_left[n]
__device__ float2 g_bd[NN];          // b_dia[n]
__device__ float4 g_BJ[NN * HC];     // b_j        (2 complex ch per float4)
__device__ float4 g_T0[NN * HC];     // jacobi ping
__device__ float4 g_T1[NN * HC];     // jacobi pong (== y at end of each order)
__device__ float2 g_OUT[NN * HC];    // real accumulator (2 ch per float2)
__device__ float2 g_XR[NN * HC];     // relu'd features between layers
__device__ float  g_S[NN];           // topk scores
__device__ unsigned long long g_thr[GG];
__device__ float g_pool[GG * HH];

__device__ __forceinline__ float4* buf(int s) {
    return s == 0 ? g_BJ : (s == 1 ? g_T0 : g_T1);
}

// ---------------- CSR construction ----------------------------------------
__global__ void k_zero_cnt() {
    for (int i = blockIdx.x * blockDim.x + threadIdx.x; i < NN; i += gridDim.x * blockDim.x) {
        g_cntR[i] = 0;
        g_cntC[i] = 0;
    }
}

__global__ void k_hist(const int* __restrict__ ei) {
    for (int e = blockIdx.x * blockDim.x + threadIdx.x; e < EE; e += gridDim.x * blockDim.x) {
        atomicAdd(&g_cntR[ei[e]], 1);
        atomicAdd(&g_cntC[ei[EE + e]], 1);
    }
}

// single-block exclusive scan of both count arrays (N=50000, 1024 threads)
__global__ void k_scan() {
    __shared__ int sm[1024];
    __shared__ int run;
    for (int which = 0; which < 2; ++which) {
        const int* cnt = which ? g_cntC : g_cntR;
        int* ptr = which ? g_cptr : g_rptr;
        if (threadIdx.x == 0) run = 0;
        __syncthreads();
        for (int base = 0; base < NN; base += 1024) {
            int i = base + threadIdx.x;
            int v = (i < NN) ? cnt[i] : 0;
            sm[threadIdx.x] = v;
            __syncthreads();
            for (int off = 1; off < 1024; off <<= 1) {
                int t = (threadIdx.x >= off) ? sm[threadIdx.x - off] : 0;
                __syncthreads();
                sm[threadIdx.x] += t;
                __syncthreads();
            }
            int incl = sm[threadIdx.x];
            int total = sm[1023];
            int base_run = run;
            __syncthreads();
            if (i < NN) ptr[i] = base_run + incl - v;
            if (threadIdx.x == 0) run = base_run + total;
            __syncthreads();
        }
        if (threadIdx.x == 0) ptr[NN] = run;
        __syncthreads();
    }
}

__global__ void k_fill(const int* __restrict__ ei) {
    for (int e = blockIdx.x * blockDim.x + threadIdx.x; e < EE; e += gridDim.x * blockDim.x) {
        int r = ei[e];
        int c = ei[EE + e];
        int p1 = g_rptr[r] + atomicAdd(&g_cntR[r], 1);
        g_adjR[p1] = c;
        int p2 = g_cptr[c] + atomicAdd(&g_cntC[c], 1);
        g_adjC[p2] = r;
    }
}

// ---------------- per-layer node parameters --------------------------------
// a = h*(deg - alpha); tmp_left = (a - i)/(a^2+1); jw = h*tmp_left
// b_dia = tmp_left*(a - i) = ((a^2-1) - 2ai)/(a^2+1)
__global__ void k_params(const float* __restrict__ h, const float* __restrict__ alpha, int l) {
    float hv = h[l], av = alpha[l];
    for (int n = blockIdx.x * blockDim.x + threadIdx.x; n < NN; n += gridDim.x * blockDim.x) {
        float deg = (float)(g_rptr[n + 1] - g_rptr[n]);
        float a = hv * (deg - av);
        float inv = 1.0f / (a * a + 1.0f);
        g_jw[n] = make_float2(hv * a * inv, -hv * inv);
        g_bd[n] = make_float2((a * a - 1.0f) * inv, -2.0f * a * inv);
    }
}

// ---------------- b_j from REAL input (j==0): also initializes OUT ---------
__global__ void k_bj_real(const float* __restrict__ x, int use_xr,
                          const float* __restrict__ c0, int l) {
    int warp = (blockIdx.x * blockDim.x + threadIdx.x) >> 5;
    int lane = threadIdx.x & 31;
    if (warp >= NN) return;
    int n = warp;
    const float2* x2 = use_xr ? (const float2*)g_XR : (const float2*)x;
    int p = g_rptr[n], end = g_rptr[n + 1];
    float ax = 0.f, ay = 0.f;
    for (; p + 4 <= end; p += 4) {
        int d0 = __ldg(&g_adjR[p]), d1 = __ldg(&g_adjR[p + 1]);
        int d2 = __ldg(&g_adjR[p + 2]), d3 = __ldg(&g_adjR[p + 3]);
        float2 v0 = __ldg(&x2[d0 * HC + lane]);
        float2 v1 = __ldg(&x2[d1 * HC + lane]);
        float2 v2 = __ldg(&x2[d2 * HC + lane]);
        float2 v3 = __ldg(&x2[d3 * HC + lane]);
        ax += v0.x + v1.x + v2.x + v3.x;
        ay += v0.y + v1.y + v2.y + v3.y;
    }
    for (; p < end; ++p) {
        int d = __ldg(&g_adjR[p]);
        float2 v = __ldg(&x2[d * HC + lane]);
        ax += v.x;
        ay += v.y;
    }
    float2 jw = g_jw[n];
    float wnx = -jw.x, wny = -jw.y;       // b_off = -h*tmp_left[row]
    float2 bd = g_bd[n];
    float2 vn = __ldg(&x2[n * HC + lane]);
    float4 b;
    b.x = wnx * ax + bd.x * vn.x;
    b.y = wny * ax + bd.y * vn.x;
    b.z = wnx * ay + bd.x * vn.y;
    b.w = wny * ay + bd.y * vn.y;
    g_BJ[n * HC + lane] = b;
    float c0v = c0[l];
    g_OUT[n * HC + lane] = make_float2(c0v * vn.x, c0v * vn.y);
}

// ---------------- b_j from COMPLEX input (j>0): reads T1 -------------------
__global__ void k_bj_cplx() {
    int warp = (blockIdx.x * blockDim.x + threadIdx.x) >> 5;
    int lane = threadIdx.x & 31;
    if (warp >= NN) return;
    int n = warp;
    const float4* Vin = g_T1;
    int p = g_rptr[n], end = g_rptr[n + 1];
    float4 a = make_float4(0.f, 0.f, 0.f, 0.f);
    for (; p + 4 <= end; p += 4) {
        int d0 = __ldg(&g_adjR[p]), d1 = __ldg(&g_adjR[p + 1]);
        int d2 = __ldg(&g_adjR[p + 2]), d3 = __ldg(&g_adjR[p + 3]);
        float4 v0 = __ldg(&Vin[d0 * HC + lane]);
        float4 v1 = __ldg(&Vin[d1 * HC + lane]);
        float4 v2 = __ldg(&Vin[d2 * HC + lane]);
        float4 v3 = __ldg(&Vin[d3 * HC + lane]);
        a.x += v0.x + v1.x + v2.x + v3.x;
        a.y += v0.y + v1.y + v2.y + v3.y;
        a.z += v0.z + v1.z + v2.z + v3.z;
        a.w += v0.w + v1.w + v2.w + v3.w;
    }
    for (; p < end; ++p) {
        int d = __ldg(&g_adjR[p]);
        float4 v = __ldg(&Vin[d * HC + lane]);
        a.x += v.x; a.y += v.y; a.z += v.z; a.w += v.w;
    }
    float2 jw = g_jw[n];
    float wnx = -jw.x, wny = -jw.y;
    float2 bd = g_bd[n];
    float4 vn = Vin[n * HC + lane];
    float4 b;
    b.x = wnx * a.x - wny * a.y + bd.x * vn.x - bd.y * vn.y;
    b.y = wnx * a.y + wny * a.x + bd.x * vn.y + bd.y * vn.x;
    b.z = wnx * a.z - wny * a.w + bd.x * vn.z - bd.y * vn.w;
    b.w = wnx * a.w + wny * a.z + bd.x * vn.w + bd.y * vn.z;
    g_BJ[n * HC + lane] = b;
}

// ---------------- jacobi: out[c] = sum_{e:col=c} jw[src] * V[src] + b_j[c] -
// FUSE: also OUT += 2*Re(cj * out)
template <bool FUSE>
__global__ void k_jac(int in_sel, int out_sel, const float* __restrict__ cj, int cjoff) {
    int warp = (blockIdx.x * blockDim.x + threadIdx.x) >> 5;
    int lane = threadIdx.x & 31;
    if (warp >= NN) return;
    int n = warp;
    const float4* Vin = buf(in_sel);
    float4* Vout = buf(out_sel);
    int p = g_cptr[n], end = g_cptr[n + 1];
    float4 acc = make_float4(0.f, 0.f, 0.f, 0.f);
    for (; p + 4 <= end; p += 4) {
        int s0 = __ldg(&g_adjC[p]), s1 = __ldg(&g_adjC[p + 1]);
        int s2 = __ldg(&g_adjC[p + 2]), s3 = __ldg(&g_adjC[p + 3]);
        float2 w0 = __ldg(&g_jw[s0]), w1 = __ldg(&g_jw[s1]);
        float2 w2 = __ldg(&g_jw[s2]), w3 = __ldg(&g_jw[s3]);
        float4 v0 = __ldg(&Vin[s0 * HC + lane]);
        float4 v1 = __ldg(&Vin[s1 * HC + lane]);
        float4 v2 = __ldg(&Vin[s2 * HC + lane]);
        float4 v3 = __ldg(&Vin[s3 * HC + lane]);
        acc.x += w0.x * v0.x - w0.y * v0.y;  acc.y += w0.x * v0.y + w0.y * v0.x;
        acc.z += w0.x * v0.z - w0.y * v0.w;  acc.w += w0.x * v0.w + w0.y * v0.z;
        acc.x += w1.x * v1.x - w1.y * v1.y;  acc.y += w1.x * v1.y + w1.y * v1.x;
        acc.z += w1.x * v1.z - w1.y * v1.w;  acc.w += w1.x * v1.w + w1.y * v1.z;
        acc.x += w2.x * v2.x - w2.y * v2.y;  acc.y += w2.x * v2.y + w2.y * v2.x;
        acc.z += w2.x * v2.z - w2.y * v2.w;  acc.w += w2.x * v2.w + w2.y * v2.z;
        acc.x += w3.x * v3.x - w3.y * v3.y;  acc.y += w3.x * v3.y + w3.y * v3.x;
        acc.z += w3.x * v3.z - w3.y * v3.w;  acc.w += w3.x * v3.w + w3.y * v3.z;
    }
    for (; p < end; ++p) {
        int s = __ldg(&g_adjC[p]);
        float2 w = __ldg(&g_jw[s]);
        float4 v = __ldg(&Vin[s * HC + lane]);
        acc.x += w.x * v.x - w.y * v.y;  acc.y += w.x * v.y + w.y * v.x;
        acc.z += w.x * v.z - w.y * v.w;  acc.w += w.x * v.w + w.y * v.z;
    }
    float4 b = g_BJ[n * HC + lane];
    acc.x += b.x; acc.y += b.y; acc.z += b.z; acc.w += b.w;
    Vout[n * HC + lane] = acc;
    if (FUSE) {
        float cr = cj[cjoff], ci = cj[cjoff + 1];
        float2 o = g_OUT[n * HC + lane];
        o.x += 2.0f * (cr * acc.x - ci * acc.y);
        o.y += 2.0f * (cr * acc.z - ci * acc.w);
        g_OUT[n * HC + lane] = o;
    }
}

// ---------------- relu: XR = max(OUT, 0) -----------------------------------
__global__ void k_relu() {
    for (int i = blockIdx.x * blockDim.x + threadIdx.x; i < NN * HC; i += gridDim.x * blockDim.x) {
        float2 o = g_OUT[i];
        g_XR[i] = make_float2(fmaxf(o.x, 0.f), fmaxf(o.y, 0.f));
    }
}

// ---------------- topk scores: s = tanh(x.w / ||w||) -----------------------
__global__ void k_scores(const float* __restrict__ tw) {
    int warp = (blockIdx.x * blockDim.x + threadIdx.x) >> 5;
    int lane = threadIdx.x & 31;
    if (warp >= NN) return;
    int n = warp;
    float2 xv = g_XR[n * HC + lane];
    float2 wv = __ldg(&((const float2*)tw)[lane]);
    float dot = xv.x * wv.x + xv.y * wv.y;
    float nsq = wv.x * wv.x + wv.y * wv.y;
    for (int off = 16; off > 0; off >>= 1) {
        dot += __shfl_xor_sync(0xFFFFFFFFu, dot, off);
        nsq += __shfl_xor_sync(0xFFFFFFFFu, nsq, off);
    }
    if (lane == 0) g_S[n] = tanhf(dot * rsqrtf(nsq));
}

__device__ __forceinline__ unsigned long long make_key(float f, int idx) {
    unsigned u = __float_as_uint(f);
    u = (u & 0x80000000u) ? ~u : (u | 0x80000000u);
    return ((unsigned long long)u << 32) | (unsigned)(0xFFFFFFFFu - (unsigned)idx);
}

// ---------------- per-graph exact k-th largest key via byte radix-select ---
__global__ void k_select() {
    __shared__ int hist[256];
    __shared__ unsigned long long s_prefix;
    __shared__ int s_kk;
    int g = blockIdx.x;
    if (threadIdx.x == 0) { s_prefix = 0ULL; s_kk = KKEEP; }
    __syncthreads();
    for (int pass = 7; pass >= 0; --pass) {
        int shift = pass * 8;
        hist[threadIdx.x] = 0;
        __syncthreads();
        unsigned long long pfx = s_prefix;
        unsigned long long maskhi = (pass == 7) ? 0ULL : ((~0ULL) << (shift + 8));
        for (int i = threadIdx.x; i < NPG; i += 256) {
            unsigned long long key = make_key(g_S[g * NPG + i], i);
            if ((key & maskhi) == (pfx & maskhi))
                atomicAdd(&hist[(int)((key >> shift) & 0xFF)], 1);
        }
        __syncthreads();
        if (threadIdx.x == 0) {
            int kk = s_kk;
            int b = 255;
            for (;;) {
                int c = hist[b];
                if (c >= kk) break;
                kk -= c;
                --b;
            }
            s_kk = kk;
            s_prefix = pfx | ((unsigned long long)b << shift);
        }
        __syncthreads();
    }
    if (threadIdx.x == 0) g_thr[g] = s_prefix;
}

// ---------------- masked mean pool: pooled[g] = sum_kept x*s / k -----------
__global__ void k_pool() {
    __shared__ float sm[256];
    int g = blockIdx.x;
    int ch = threadIdx.x & 63;
    int nl = threadIdx.x >> 6;   // 0..3
    unsigned long long thr = g_thr[g];
    const float* xr = (const float*)g_XR;
    float acc = 0.f;
    for (int i = nl; i < NPG; i += 4) {
        int node = g * NPG + i;
        float sv = g_S[node];
        if (make_key(sv, i) >= thr)
            acc += xr[node * HH + ch] * sv;
    }
    sm[threadIdx.x] = acc;
    __syncthreads();
    if (nl == 0) {
        float t = sm[ch] + sm[64 + ch] + sm[128 + ch] + sm[192 + ch];
        g_pool[g * HH + ch] = t * (1.0f / (float)KKEEP);
    }
}

// ---------------- final linear: out[g,o] = pooled[g] . W[:,o] + b[o] -------
__global__ void k_linear(const float* __restrict__ lw, const float* __restrict__ lb,
                         float* __restrict__ out) {
    int t = threadIdx.x;
    if (t >= GG * 10) return;
    int g = t / 10, o = t % 10;
    float acc = lb[o];
    #pragma unroll
    for (int h = 0; h < HH; ++h)
        acc += g_pool[g * HH + h] * lw[h * 10 + o];
    out[g * 10 + o] = acc;
}

// ---------------------------------------------------------------------------
extern "C" void kernel_launch(void* const* d_in, const int* in_sizes, int n_in,
                              void* d_out, int out_size) {
    const float* x     = (const float*)d_in[0];
    const int*   ei    = (const int*)d_in[1];
    // d_in[2] = batch (unused: equal-size sorted graphs)
    const float* h     = (const float*)d_in[3];
    const float* alpha = (const float*)d_in[4];
    const float* c0    = (const float*)d_in[5];
    const float* cj    = (const float*)d_in[6];
    const float* tw    = (const float*)d_in[7];
    const float* lw    = (const float*)d_in[8];
    const float* lb    = (const float*)d_in[9];
    float* out = (float*)d_out;

    const int SPMM_GRID = (NN * 32 + 255) / 256;   // warp per node, 8 warps/block

    // CSR build (both directions)
    k_zero_cnt<<<196, 256>>>();
    k_hist<<<1024, 256>>>(ei);
    k_scan<<<1, 1024>>>();
    k_zero_cnt<<<196, 256>>>();
    k_fill<<<1024, 256>>>(ei);

    for (int l = 0; l < 2; ++l) {
        k_params<<<(NN + 255) / 256, 256>>>(h, alpha, l);
        for (int j = 0; j < 3; ++j) {
            if (j == 0)
                k_bj_real<<<SPMM_GRID, 256>>>(x, l, c0, l);   // use_xr = (l != 0)
            else
                k_bj_cplx<<<SPMM_GRID, 256>>>();
            int cjoff = (l * 3 + j) * 2;
            // 4 jacobi iterations: BJ -> T0 -> T1 -> T0 -> T1(final, fused out-accum)
            k_jac<false><<<SPMM_GRID, 256>>>(0, 1, cj, cjoff);
            k_jac<false><<<SPMM_GRID, 256>>>(1, 2, cj, cjoff);
            k_jac<false><<<SPMM_GRID, 256>>>(2, 1, cj, cjoff);
            k_jac<true><<<SPMM_GRID, 256>>>(1, 2, cj, cjoff);
        }
        k_relu<<<1024, 256>>>();
    }

    k_scores<<<SPMM_GRID, 256>>>(tw);
    k_select<<<GG, 256>>>();
    k_pool<<<GG, 256>>>();
    k_linear<<<1, 128>>>(lw, lb, out);
}

// round 3
// speedup vs baseline: 1.5074x; 1.5074x over previous
#include <cuda_runtime.h>
#include <cuda_fp16.h>

// ---------------------------------------------------------------------------
// CayleyNet: 2x CayleyConv (R=3, K=4 Jacobi) + TopKPooling(0.9) + mean pool + linear
// N=50000 nodes, E=800000 edges, H=64 channels, G=10 graphs (5000 nodes each)
// fp16 intermediate storage, fp32 accumulation, jw-folded Jacobi (z = jw*y)
// ---------------------------------------------------------------------------

#define NN    50000
#define EE    800000
#define HH    64
#define HC    32          // lanes per node: lane = 2 complex channels
#define GG    10
#define NPG   5000
#define KKEEP 4500        // ceil(0.9 * 5000)

// ---------------- static device scratch (no allocations allowed) ----------
__device__ int g_cntR[NN];
__device__ int g_cntC[NN];
__device__ int g_rptr[NN + 1];
__device__ int g_cptr[NN + 1];
__device__ int g_adjR[EE];             // grouped by row: stores col (dst)
__device__ int g_adjC[EE];             // grouped by col: stores row (src)
__device__ float2 g_jw[NN];            // h * tmp_left[n]
__device__ float2 g_bd[NN];            // b_dia[n]
__device__ float4 g_BJ[NN * HC];       // b_j (fp32, 2 complex ch per float4)
__device__ uint2  g_Z0[NN * HC];       // z = jw*y   (fp16 x4) ping
__device__ uint2  g_Z1[NN * HC];       // z pong
__device__ uint2  g_Y16[NN * HC];      // final y per order (fp16 x4)
__device__ float2 g_OUT[NN * HC];      // real accumulator (fp32, 2 ch)
__device__ unsigned g_XH[NN * HC];     // fp16 copy of input x (2 real ch, packed half2)
__device__ unsigned g_XR[NN * HC];     // relu'd features between layers (packed half2)
__device__ float  g_S[NN];             // topk scores
__device__ unsigned long long g_thr[GG];
__device__ float g_pool[GG * HH];

__device__ __forceinline__ uint2* zbuf(int s) { return s ? g_Z1 : g_Z0; }

// register-friendly reinterpret helpers: union with constant indices only
union H4U {
    uint2 u;
    __half2 h[2];
};
union H2U {
    unsigned u;
    __half2 h;
};

__device__ __forceinline__ float4 h4_to_f4(uint2 v) {
    H4U c;
    c.u = v;
    float2 fa = __half22float2(c.h[0]);
    float2 fb = __half22float2(c.h[1]);
    return make_float4(fa.x, fa.y, fb.x, fb.y);
}
__device__ __forceinline__ uint2 f4_to_h4(float4 f) {
    H4U c;
    c.h[0] = __float22half2_rn(make_float2(f.x, f.y));
    c.h[1] = __float22half2_rn(make_float2(f.z, f.w));
    return c.u;
}
__device__ __forceinline__ float2 h2_to_f2(unsigned v) {
    H2U c;
    c.u = v;
    return __half22float2(c.h);
}
__device__ __forceinline__ unsigned f2_to_h2(float2 f) {
    H2U c;
    c.h = __float22half2_rn(f);
    return c.u;
}

// ---------------- CSR construction ----------------------------------------
__global__ void k_zero_cnt() {
    for (int i = blockIdx.x * blockDim.x + threadIdx.x; i < NN; i += gridDim.x * blockDim.x) {
        g_cntR[i] = 0;
        g_cntC[i] = 0;
    }
}

__global__ void k_hist(const int* __restrict__ ei) {
    for (int e = blockIdx.x * blockDim.x + threadIdx.x; e < EE; e += gridDim.x * blockDim.x) {
        atomicAdd(&g_cntR[ei[e]], 1);
        atomicAdd(&g_cntC[ei[EE + e]], 1);
    }
}

// 2 blocks: block 0 scans cntR->rptr, block 1 scans cntC->cptr.
// Thread t owns 49 consecutive elements; one block-scan of per-thread sums.
__global__ void k_scan() {
    __shared__ int sm[1024];
    const int PER = 49;
    int which = blockIdx.x;
    const int* cnt = which ? g_cntC : g_cntR;
    int* ptr = which ? g_cptr : g_rptr;
    int t = threadIdx.x;
    int base = t * PER;
    int local = 0;
    for (int i = 0; i < PER; ++i) {
        int idx = base + i;
        if (idx < NN) local += cnt[idx];
    }
    sm[t] = local;
    __syncthreads();
    for (int off = 1; off < 1024; off <<= 1) {
        int v = (t >= off) ? sm[t - off] : 0;
        __syncthreads();
        sm[t] += v;
        __syncthreads();
    }
    int run = sm[t] - local;           // exclusive prefix of this chunk
    for (int i = 0; i < PER; ++i) {
        int idx = base + i;
        if (idx < NN) {
            int c = cnt[idx];
            ptr[idx] = run;
            run += c;
        }
    }
    if (t == 1023) ptr[NN] = sm[1023];
}

__global__ void k_fill(const int* __restrict__ ei) {
    for (int e = blockIdx.x * blockDim.x + threadIdx.x; e < EE; e += gridDim.x * blockDim.x) {
        int r = ei[e];
        int c = ei[EE + e];
        int p1 = g_rptr[r] + atomicAdd(&g_cntR[r], 1);
        g_adjR[p1] = c;
        int p2 = g_cptr[c] + atomicAdd(&g_cntC[c], 1);
        g_adjC[p2] = r;
    }
}

// ---------------- x -> fp16 copy -------------------------------------------
__global__ void k_x2h(const float* __restrict__ x) {
    for (int i = blockIdx.x * blockDim.x + threadIdx.x; i < NN * HC; i += gridDim.x * blockDim.x) {
        float2 v = ((const float2*)x)[i];
        g_XH[i] = f2_to_h2(v);
    }
}

// ---------------- per-layer node parameters --------------------------------
// a = h*(deg - alpha); jw = h*tmp_left = h*(a - i)/(a^2+1)
// b_dia = tmp_left*(a - i) = ((a^2-1) - 2ai)/(a^2+1)
__global__ void k_params(const float* __restrict__ h, const float* __restrict__ alpha, int l) {
    float hv = h[l], av = alpha[l];
    for (int n = blockIdx.x * blockDim.x + threadIdx.x; n < NN; n += gridDim.x * blockDim.x) {
        float deg = (float)(g_rptr[n + 1] - g_rptr[n]);
        float a = hv * (deg - av);
        float inv = 1.0f / (a * a + 1.0f);
        g_jw[n] = make_float2(hv * a * inv, -hv * inv);
        g_bd[n] = make_float2((a * a - 1.0f) * inv, -2.0f * a * inv);
    }
}

// ---------------- b_j from REAL fp16 input (j==0): also init OUT, Z0 -------
// use_xr selects g_XR (layer 1) vs g_XH (layer 0) inside device code.
__global__ void k_bj_real(int use_xr, const float* __restrict__ c0, int l) {
    int warp = (blockIdx.x * blockDim.x + threadIdx.x) >> 5;
    int lane = threadIdx.x & 31;
    if (warp >= NN) return;
    int n = warp;
    const unsigned* __restrict__ X = use_xr ? g_XR : g_XH;
    int p = g_rptr[n], end = g_rptr[n + 1];
    float sx = 0.f, sy = 0.f;
    for (; p + 8 <= end; p += 8) {
        int d0 = __ldg(&g_adjR[p + 0]), d1 = __ldg(&g_adjR[p + 1]);
        int d2 = __ldg(&g_adjR[p + 2]), d3 = __ldg(&g_adjR[p + 3]);
        int d4 = __ldg(&g_adjR[p + 4]), d5 = __ldg(&g_adjR[p + 5]);
        int d6 = __ldg(&g_adjR[p + 6]), d7 = __ldg(&g_adjR[p + 7]);
        float2 f0 = h2_to_f2(__ldg(&X[d0 * HC + lane]));
        float2 f1 = h2_to_f2(__ldg(&X[d1 * HC + lane]));
        float2 f2 = h2_to_f2(__ldg(&X[d2 * HC + lane]));
        float2 f3 = h2_to_f2(__ldg(&X[d3 * HC + lane]));
        float2 f4 = h2_to_f2(__ldg(&X[d4 * HC + lane]));
        float2 f5 = h2_to_f2(__ldg(&X[d5 * HC + lane]));
        float2 f6 = h2_to_f2(__ldg(&X[d6 * HC + lane]));
        float2 f7 = h2_to_f2(__ldg(&X[d7 * HC + lane]));
        sx += f0.x + f1.x + f2.x + f3.x + f4.x + f5.x + f6.x + f7.x;
        sy += f0.y + f1.y + f2.y + f3.y + f4.y + f5.y + f6.y + f7.y;
    }
    for (; p < end; ++p) {
        int d = __ldg(&g_adjR[p]);
        float2 f = h2_to_f2(__ldg(&X[d * HC + lane]));
        sx += f.x;
        sy += f.y;
    }
    float2 jwv = g_jw[n];
    float wnx = -jwv.x, wny = -jwv.y;     // b_off weight is constant per row
    float2 bdv = g_bd[n];
    float2 vn = h2_to_f2(__ldg(&X[n * HC + lane]));
    float4 b;
    b.x = wnx * sx + bdv.x * vn.x;
    b.y = wny * sx + bdv.y * vn.x;
    b.z = wnx * sy + bdv.x * vn.y;
    b.w = wny * sy + bdv.y * vn.y;
    int idx = n * HC + lane;
    g_BJ[idx] = b;
    float4 z;                              // z0 = jw * b
    z.x = jwv.x * b.x - jwv.y * b.y;
    z.y = jwv.x * b.y + jwv.y * b.x;
    z.z = jwv.x * b.z - jwv.y * b.w;
    z.w = jwv.x * b.w + jwv.y * b.z;
    g_Z0[idx] = f4_to_h4(z);
    float c0v = __ldg(&c0[l]);
    g_OUT[idx] = make_float2(c0v * vn.x, c0v * vn.y);
}

// ---------------- b_j from COMPLEX fp16 input (j>0): reads Y16 -------------
__global__ void k_bj_cplx() {
    int warp = (blockIdx.x * blockDim.x + threadIdx.x) >> 5;
    int lane = threadIdx.x & 31;
    if (warp >= NN) return;
    int n = warp;
    int p = g_rptr[n], end = g_rptr[n + 1];
    float4 a = make_float4(0.f, 0.f, 0.f, 0.f);
    for (; p + 8 <= end; p += 8) {
        int d0 = __ldg(&g_adjR[p + 0]), d1 = __ldg(&g_adjR[p + 1]);
        int d2 = __ldg(&g_adjR[p + 2]), d3 = __ldg(&g_adjR[p + 3]);
        int d4 = __ldg(&g_adjR[p + 4]), d5 = __ldg(&g_adjR[p + 5]);
        int d6 = __ldg(&g_adjR[p + 6]), d7 = __ldg(&g_adjR[p + 7]);
        float4 v0 = h4_to_f4(__ldg(&g_Y16[d0 * HC + lane]));
        float4 v1 = h4_to_f4(__ldg(&g_Y16[d1 * HC + lane]));
        float4 v2 = h4_to_f4(__ldg(&g_Y16[d2 * HC + lane]));
        float4 v3 = h4_to_f4(__ldg(&g_Y16[d3 * HC + lane]));
        float4 v4 = h4_to_f4(__ldg(&g_Y16[d4 * HC + lane]));
        float4 v5 = h4_to_f4(__ldg(&g_Y16[d5 * HC + lane]));
        float4 v6 = h4_to_f4(__ldg(&g_Y16[d6 * HC + lane]));
        float4 v7 = h4_to_f4(__ldg(&g_Y16[d7 * HC + lane]));
        a.x += v0.x + v1.x + v2.x + v3.x + v4.x + v5.x + v6.x + v7.x;
        a.y += v0.y + v1.y + v2.y + v3.y + v4.y + v5.y + v6.y + v7.y;
        a.z += v0.z + v1.z + v2.z + v3.z + v4.z + v5.z + v6.z + v7.z;
        a.w += v0.w + v1.w + v2.w + v3.w + v4.w + v5.w + v6.w + v7.w;
    }
    for (; p < end; ++p) {
        int d = __ldg(&g_adjR[p]);
        float4 v = h4_to_f4(__ldg(&g_Y16[d * HC + lane]));
        a.x += v.x; a.y += v.y; a.z += v.z; a.w += v.w;
    }
    float2 jwv = g_jw[n];
    float wnx = -jwv.x, wny = -jwv.y;
    float2 bdv = g_bd[n];
    int idx = n * HC + lane;
    float4 vn = h4_to_f4(g_Y16[idx]);
    float4 b;
    b.x = wnx * a.x - wny * a.y + bdv.x * vn.x - bdv.y * vn.y;
    b.y = wnx * a.y + wny * a.x + bdv.x * vn.y + bdv.y * vn.x;
    b.z = wnx * a.z - wny * a.w + bdv.x * vn.z - bdv.y * vn.w;
    b.w = wnx * a.w + wny * a.z + bdv.x * vn.w + bdv.y * vn.z;
    g_BJ[idx] = b;
    float4 z;                              // z0 = jw * b
    z.x = jwv.x * b.x - jwv.y * b.y;
    z.y = jwv.x * b.y + jwv.y * b.x;
    z.z = jwv.x * b.z - jwv.y * b.w;
    z.w = jwv.x * b.w + jwv.y * b.z;
    g_Z0[idx] = f4_to_h4(z);
}

// ---------------- jacobi: y[n] = sum_{e:col=n} z[src] + b_j[n] -------------
// non-final: write z_out = jw*y (fp16). final: write Y16=y, OUT += 2*Re(cj*y)
template <bool FINAL>
__global__ void k_jac(int in_sel, int out_sel, const float* __restrict__ cj, int cjoff) {
    int warp = (blockIdx.x * blockDim.x + threadIdx.x) >> 5;
    int lane = threadIdx.x & 31;
    if (warp >= NN) return;
    int n = warp;
    const uint2* __restrict__ Zin = zbuf(in_sel);
    int p = g_cptr[n], end = g_cptr[n + 1];
    float4 acc = make_float4(0.f, 0.f, 0.f, 0.f);
    for (; p + 8 <= end; p += 8) {
        int s0 = __ldg(&g_adjC[p + 0]), s1 = __ldg(&g_adjC[p + 1]);
        int s2 = __ldg(&g_adjC[p + 2]), s3 = __ldg(&g_adjC[p + 3]);
        int s4 = __ldg(&g_adjC[p + 4]), s5 = __ldg(&g_adjC[p + 5]);
        int s6 = __ldg(&g_adjC[p + 6]), s7 = __ldg(&g_adjC[p + 7]);
        float4 v0 = h4_to_f4(__ldg(&Zin[s0 * HC + lane]));
        float4 v1 = h4_to_f4(__ldg(&Zin[s1 * HC + lane]));
        float4 v2 = h4_to_f4(__ldg(&Zin[s2 * HC + lane]));
        float4 v3 = h4_to_f4(__ldg(&Zin[s3 * HC + lane]));
        float4 v4 = h4_to_f4(__ldg(&Zin[s4 * HC + lane]));
        float4 v5 = h4_to_f4(__ldg(&Zin[s5 * HC + lane]));
        float4 v6 = h4_to_f4(__ldg(&Zin[s6 * HC + lane]));
        float4 v7 = h4_to_f4(__ldg(&Zin[s7 * HC + lane]));
        acc.x += v0.x + v1.x + v2.x + v3.x + v4.x + v5.x + v6.x + v7.x;
        acc.y += v0.y + v1.y + v2.y + v3.y + v4.y + v5.y + v6.y + v7.y;
        acc.z += v0.z + v1.z + v2.z + v3.z + v4.z + v5.z + v6.z + v7.z;
        acc.w += v0.w + v1.w + v2.w + v3.w + v4.w + v5.w + v6.w + v7.w;
    }
    for (; p < end; ++p) {
        int s = __ldg(&g_adjC[p]);
        float4 v = h4_to_f4(__ldg(&Zin[s * HC + lane]));
        acc.x += v.x; acc.y += v.y; acc.z += v.z; acc.w += v.w;
    }
    int idx = n * HC + lane;
    float4 b = g_BJ[idx];
    acc.x += b.x; acc.y += b.y; acc.z += b.z; acc.w += b.w;   // acc = y
    if (!FINAL) {
        float2 jwv = g_jw[n];
        float4 z;
        z.x = jwv.x * acc.x - jwv.y * acc.y;
        z.y = jwv.x * acc.y + jwv.y * acc.x;
        z.z = jwv.x * acc.z - jwv.y * acc.w;
        z.w = jwv.x * acc.w + jwv.y * acc.z;
        zbuf(out_sel)[idx] = f4_to_h4(z);
    } else {
        g_Y16[idx] = f4_to_h4(acc);
        float cr = __ldg(&cj[cjoff]), ci = __ldg(&cj[cjoff + 1]);
        float2 o = g_OUT[idx];
        o.x += 2.0f * (cr * acc.x - ci * acc.y);
        o.y += 2.0f * (cr * acc.z - ci * acc.w);
        g_OUT[idx] = o;
    }
}

// ---------------- relu: XR = fp16(max(OUT, 0)) -----------------------------
__global__ void k_relu() {
    for (int i = blockIdx.x * blockDim.x + threadIdx.x; i < NN * HC; i += gridDim.x * blockDim.x) {
        float2 o = g_OUT[i];
        g_XR[i] = f2_to_h2(make_float2(fmaxf(o.x, 0.f), fmaxf(o.y, 0.f)));
    }
}

// ---------------- topk scores: s = tanh(x.w / ||w||) -----------------------
__global__ void k_scores(const float* __restrict__ tw) {
    int warp = (blockIdx.x * blockDim.x + threadIdx.x) >> 5;
    int lane = threadIdx.x & 31;
    if (warp >= NN) return;
    int n = warp;
    float2 xv = h2_to_f2(g_XR[n * HC + lane]);
    float2 wv = __ldg(&((const float2*)tw)[lane]);
    float dot = xv.x * wv.x + xv.y * wv.y;
    float nsq = wv.x * wv.x + wv.y * wv.y;
    for (int off = 16; off > 0; off >>= 1) {
        dot += __shfl_xor_sync(0xFFFFFFFFu, dot, off);
        nsq += __shfl_xor_sync(0xFFFFFFFFu, nsq, off);
    }
    if (lane == 0) g_S[n] = tanhf(dot * rsqrtf(nsq));
}

__device__ __forceinline__ unsigned long long make_key(float f, int idx) {
    unsigned u = __float_as_uint(f);
    u = (u & 0x80000000u) ? ~u : (u | 0x80000000u);
    return ((unsigned long long)u << 32) | (unsigned)(0xFFFFFFFFu - (unsigned)idx);
}

// ---------------- per-graph exact k-th largest key via byte radix-select ---
__global__ void k_select() {
    __shared__ int hist[256];
    __shared__ unsigned long long s_prefix;
    __shared__ int s_kk;
    int g = blockIdx.x;
    if (threadIdx.x == 0) { s_prefix = 0ULL; s_kk = KKEEP; }
    __syncthreads();
    for (int pass = 7; pass >= 0; --pass) {
        int shift = pass * 8;
        hist[threadIdx.x] = 0;
        __syncthreads();
        unsigned long long pfx = s_prefix;
        unsigned long long maskhi = (pass == 7) ? 0ULL : ((~0ULL) << (shift + 8));
        for (int i = threadIdx.x; i < NPG; i += 256) {
            unsigned long long key = make_key(g_S[g * NPG + i], i);
            if ((key & maskhi) == (pfx & maskhi))
                atomicAdd(&hist[(int)((key >> shift) & 0xFF)], 1);
        }
        __syncthreads();
        if (threadIdx.x == 0) {
            int kk = s_kk;
            int b = 255;
            for (;;) {
                int c = hist[b];
                if (c >= kk) break;
                kk -= c;
                --b;
            }
            s_kk = kk;
            s_prefix = pfx | ((unsigned long long)b << shift);
        }
        __syncthreads();
    }
    if (threadIdx.x == 0) g_thr[g] = s_prefix;
}

// ---------------- masked mean pool: pooled[g] = sum_kept x*s / k -----------
__global__ void k_pool() {
    __shared__ float sm[256];
    int g = blockIdx.x;
    int ch = threadIdx.x & 63;
    int nl = threadIdx.x >> 6;   // 0..3
    unsigned long long thr = g_thr[g];
    float acc = 0.f;
    for (int i = nl; i < NPG; i += 4) {
        int node = g * NPG + i;
        float sv = g_S[node];
        if (make_key(sv, i) >= thr) {
            float2 f = h2_to_f2(g_XR[node * HC + (ch >> 1)]);
            acc += ((ch & 1) ? f.y : f.x) * sv;
        }
    }
    sm[threadIdx.x] = acc;
    __syncthreads();
    if (nl == 0) {
        float t = sm[ch] + sm[64 + ch] + sm[128 + ch] + sm[192 + ch];
        g_pool[g * HH + ch] = t * (1.0f / (float)KKEEP);
    }
}

// ---------------- final linear: out[g,o] = pooled[g] . W[:,o] + b[o] -------
__global__ void k_linear(const float* __restrict__ lw, const float* __restrict__ lb,
                         float* __restrict__ out) {
    int t = threadIdx.x;
    if (t >= GG * 10) return;
    int g = t / 10, o = t % 10;
    float acc = lb[o];
    #pragma unroll
    for (int h = 0; h < HH; ++h)
        acc += g_pool[g * HH + h] * lw[h * 10 + o];
    out[g * 10 + o] = acc;
}

// ---------------------------------------------------------------------------
extern "C" void kernel_launch(void* const* d_in, const int* in_sizes, int n_in,
                              void* d_out, int out_size) {
    const float* x     = (const float*)d_in[0];
    const int*   ei    = (const int*)d_in[1];
    // d_in[2] = batch (unused: equal-size sorted graphs)
    const float* h     = (const float*)d_in[3];
    const float* alpha = (const float*)d_in[4];
    const float* c0    = (const float*)d_in[5];
    const float* cj    = (const float*)d_in[6];
    const float* tw    = (const float*)d_in[7];
    const float* lw    = (const float*)d_in[8];
    const float* lb    = (const float*)d_in[9];
    float* out = (float*)d_out;

    const int SPMM_GRID = (NN * 32 + 255) / 256;   // warp per node, 8 warps/block

    // CSR build (both directions)
    k_zero_cnt<<<196, 256>>>();
    k_hist<<<1024, 256>>>(ei);
    k_scan<<<2, 1024>>>();
    k_zero_cnt<<<196, 256>>>();
    k_fill<<<1024, 256>>>(ei);
    k_x2h<<<1024, 256>>>(x);

    for (int l = 0; l < 2; ++l) {
        k_params<<<(NN + 255) / 256, 256>>>(h, alpha, l);
        for (int j = 0; j < 3; ++j) {
            if (j == 0)
                k_bj_real<<<SPMM_GRID, 256>>>(l, c0, l);   // use_xr = (l != 0)
            else
                k_bj_cplx<<<SPMM_GRID, 256>>>();
            int cjoff = (l * 3 + j) * 2;
            // 4 jacobi iterations: Z0 -> Z1 -> Z0 -> Z1 -> (final: Y16 + OUT)
            k_jac<false><<<SPMM_GRID, 256>>>(0, 1, cj, cjoff);
            k_jac<false><<<SPMM_GRID, 256>>>(1, 0, cj, cjoff);
            k_jac<false><<<SPMM_GRID, 256>>>(0, 1, cj, cjoff);
            k_jac<true><<<SPMM_GRID, 256>>>(1, 0, cj, cjoff);
        }
        k_relu<<<1024, 256>>>();
    }

    k_scores<<<SPMM_GRID, 256>>>(tw);
    k_select<<<GG, 256>>>();
    k_pool<<<GG, 256>>>();
    k_linear<<<1, 128>>>(lw, lb, out);
}

// round 4
// speedup vs baseline: 1.5187x; 1.0075x over previous
#include <cuda_runtime.h>
#include <cuda_fp16.h>

// ---------------------------------------------------------------------------
// CayleyNet: 2x CayleyConv (R=3, K=4 Jacobi) + TopKPooling(0.9) + mean pool + linear
// fp16 storage everywhere (z, y, BJ, x), fp32 accumulation, jw-folded Jacobi,
// fused relu/scores epilogues, degree-sorted scheduling.
// ---------------------------------------------------------------------------

#define NN    50000
#define EE    800000
#define HH    64
#define HC    32          // lanes per node: lane = 2 complex channels
#define GG    10
#define NPG   5000
#define KKEEP 4500        // ceil(0.9 * 5000)
#define DB    1024        // degree bins

// ---------------- static device scratch (no allocations allowed) ----------
__device__ int g_cntR[NN];
__device__ int g_cntC[NN];
__device__ int g_rptr[NN + 1];
__device__ int g_cptr[NN + 1];
__device__ int g_adjR[EE];             // grouped by row: stores col (dst)
__device__ int g_adjC[EE];             // grouped by col: stores row (src)
__device__ int g_dhR[DB];              // degree histogram / cursors (row)
__device__ int g_dhC[DB];              // degree histogram / cursors (col)
__device__ int g_ordR[NN];             // nodes sorted by row-degree desc
__device__ int g_ordC[NN];             // nodes sorted by col-degree desc
__device__ float2 g_jw[NN];            // h * tmp_left[n]
__device__ float2 g_bd[NN];            // b_dia[n]
__device__ uint2  g_BJ[NN * HC];       // b_j (fp16 x4)
__device__ uint2  g_Z0[NN * HC];       // z = jw*y (fp16 x4) ping
__device__ uint2  g_Z1[NN * HC];       // z pong
__device__ uint2  g_Y16[NN * HC];      // final y per order (fp16 x4)
__device__ float2 g_OUT[NN * HC];      // real accumulator (fp32, 2 ch)
__device__ unsigned g_XH[NN * HC];     // fp16 copy of input x (packed half2)
__device__ unsigned g_XR[NN * HC];     // relu'd features (packed half2)
__device__ float  g_S[NN];             // topk scores
__device__ unsigned long long g_thr[GG];
__device__ float g_pool[GG * HH];

__device__ __forceinline__ uint2* zbuf(int s) { return s ? g_Z1 : g_Z0; }

// register-friendly reinterpret helpers
union H4U { uint2 u; __half2 h[2]; };
union H2U { unsigned u; __half2 h; };

__device__ __forceinline__ float4 h4_to_f4(uint2 v) {
    H4U c; c.u = v;
    float2 fa = __half22float2(c.h[0]);
    float2 fb = __half22float2(c.h[1]);
    return make_float4(fa.x, fa.y, fb.x, fb.y);
}
__device__ __forceinline__ uint2 f4_to_h4(float4 f) {
    H4U c;
    c.h[0] = __float22half2_rn(make_float2(f.x, f.y));
    c.h[1] = __float22half2_rn(make_float2(f.z, f.w));
    return c.u;
}
__device__ __forceinline__ float2 h2_to_f2(unsigned v) {
    H2U c; c.u = v;
    return __half22float2(c.h);
}
__device__ __forceinline__ unsigned f2_to_h2(float2 f) {
    H2U c; c.h = __float22half2_rn(f);
    return c.u;
}

// ---------------- CSR construction ----------------------------------------
__global__ void k_zero() {
    int i = blockIdx.x * blockDim.x + threadIdx.x;
    for (; i < NN; i += gridDim.x * blockDim.x) {
        g_cntR[i] = 0;
        g_cntC[i] = 0;
        if (i < DB) { g_dhR[i] = 0; g_dhC[i] = 0; }
    }
}

__global__ void k_hist(const int* __restrict__ ei) {
    for (int e = blockIdx.x * blockDim.x + threadIdx.x; e < EE; e += gridDim.x * blockDim.x) {
        atomicAdd(&g_cntR[ei[e]], 1);
        atomicAdd(&g_cntC[ei[EE + e]], 1);
    }
}

// 2 blocks: block 0 scans cntR->rptr, block 1 scans cntC->cptr.
// Also rewrites cnt[i] = start offset (fill cursor).
__global__ void k_scan() {
    __shared__ int sm[1024];
    const int PER = 49;
    int which = blockIdx.x;
    int* cnt = which ? g_cntC : g_cntR;
    int* ptr = which ? g_cptr : g_rptr;
    int t = threadIdx.x;
    int base = t * PER;
    int local = 0;
    for (int i = 0; i < PER; ++i) {
        int idx = base + i;
        if (idx < NN) local += cnt[idx];
    }
    sm[t] = local;
    __syncthreads();
    for (int off = 1; off < 1024; off <<= 1) {
        int v = (t >= off) ? sm[t - off] : 0;
        __syncthreads();
        sm[t] += v;
        __syncthreads();
    }
    int run = sm[t] - local;
    for (int i = 0; i < PER; ++i) {
        int idx = base + i;
        if (idx < NN) {
            int c = cnt[idx];
            ptr[idx] = run;
            cnt[idx] = run;     // cursor for k_fill
            run += c;
        }
    }
    if (t == 1023) ptr[NN] = sm[1023];
}

__global__ void k_fill(const int* __restrict__ ei) {
    for (int e = blockIdx.x * blockDim.x + threadIdx.x; e < EE; e += gridDim.x * blockDim.x) {
        int r = ei[e];
        int c = ei[EE + e];
        g_adjR[atomicAdd(&g_cntR[r], 1)] = c;
        g_adjC[atomicAdd(&g_cntC[c], 1)] = r;
    }
}

// ---------------- degree-descending counting sort --------------------------
__global__ void k_deg_hist() {
    for (int n = blockIdx.x * blockDim.x + threadIdx.x; n < NN; n += gridDim.x * blockDim.x) {
        int dR = min(g_rptr[n + 1] - g_rptr[n], DB - 1);
        int dC = min(g_cptr[n + 1] - g_cptr[n], DB - 1);
        atomicAdd(&g_dhR[dR], 1);
        atomicAdd(&g_dhC[dC], 1);
    }
}

// descending starts: start[d] = #nodes with deg > d. 2 blocks.
__global__ void k_deg_scan() {
    __shared__ int sm[DB];
    int* dh = blockIdx.x ? g_dhC : g_dhR;
    int t = threadIdx.x;
    int rv = dh[DB - 1 - t];          // reversed
    sm[t] = rv;
    __syncthreads();
    for (int off = 1; off < DB; off <<= 1) {
        int v = (t >= off) ? sm[t - off] : 0;
        __syncthreads();
        sm[t] += v;
        __syncthreads();
    }
    dh[DB - 1 - t] = sm[t] - rv;      // exclusive prefix in descending order
}

__global__ void k_deg_fill() {
    for (int n = blockIdx.x * blockDim.x + threadIdx.x; n < NN; n += gridDim.x * blockDim.x) {
        int dR = min(g_rptr[n + 1] - g_rptr[n], DB - 1);
        int dC = min(g_cptr[n + 1] - g_cptr[n], DB - 1);
        g_ordR[atomicAdd(&g_dhR[dR], 1)] = n;
        g_ordC[atomicAdd(&g_dhC[dC], 1)] = n;
    }
}

// ---------------- x -> fp16 copy -------------------------------------------
__global__ void k_x2h(const float* __restrict__ x) {
    for (int i = blockIdx.x * blockDim.x + threadIdx.x; i < NN * HC; i += gridDim.x * blockDim.x) {
        float2 v = ((const float2*)x)[i];
        g_XH[i] = f2_to_h2(v);
    }
}

// ---------------- per-layer node parameters --------------------------------
__global__ void k_params(const float* __restrict__ h, const float* __restrict__ alpha, int l) {
    float hv = h[l], av = alpha[l];
    for (int n = blockIdx.x * blockDim.x + threadIdx.x; n < NN; n += gridDim.x * blockDim.x) {
        float deg = (float)(g_rptr[n + 1] - g_rptr[n]);
        float a = hv * (deg - av);
        float inv = 1.0f / (a * a + 1.0f);
        g_jw[n] = make_float2(hv * a * inv, -hv * inv);
        g_bd[n] = make_float2((a * a - 1.0f) * inv, -2.0f * a * inv);
    }
}

// ---------------- b_j from REAL fp16 input (j==0): also init OUT, Z0 -------
__global__ void k_bj_real(int use_xr, const float* __restrict__ c0, int l) {
    int warp = (blockIdx.x * blockDim.x + threadIdx.x) >> 5;
    int lane = threadIdx.x & 31;
    if (warp >= NN) return;
    int n = g_ordR[warp];
    const unsigned* __restrict__ X = use_xr ? g_XR : g_XH;
    int p = g_rptr[n], end = g_rptr[n + 1];
    float sx = 0.f, sy = 0.f;
    for (; p + 8 <= end; p += 8) {
        int d0 = __ldg(&g_adjR[p + 0]), d1 = __ldg(&g_adjR[p + 1]);
        int d2 = __ldg(&g_adjR[p + 2]), d3 = __ldg(&g_adjR[p + 3]);
        int d4 = __ldg(&g_adjR[p + 4]), d5 = __ldg(&g_adjR[p + 5]);
        int d6 = __ldg(&g_adjR[p + 6]), d7 = __ldg(&g_adjR[p + 7]);
        float2 f0 = h2_to_f2(__ldg(&X[d0 * HC + lane]));
        float2 f1 = h2_to_f2(__ldg(&X[d1 * HC + lane]));
        float2 f2 = h2_to_f2(__ldg(&X[d2 * HC + lane]));
        float2 f3 = h2_to_f2(__ldg(&X[d3 * HC + lane]));
        float2 f4 = h2_to_f2(__ldg(&X[d4 * HC + lane]));
        float2 f5 = h2_to_f2(__ldg(&X[d5 * HC + lane]));
        float2 f6 = h2_to_f2(__ldg(&X[d6 * HC + lane]));
        float2 f7 = h2_to_f2(__ldg(&X[d7 * HC + lane]));
        sx += f0.x + f1.x + f2.x + f3.x + f4.x + f5.x + f6.x + f7.x;
        sy += f0.y + f1.y + f2.y + f3.y + f4.y + f5.y + f6.y + f7.y;
    }
    for (; p < end; ++p) {
        int d = __ldg(&g_adjR[p]);
        float2 f = h2_to_f2(__ldg(&X[d * HC + lane]));
        sx += f.x;
        sy += f.y;
    }
    float2 jwv = g_jw[n];
    float wnx = -jwv.x, wny = -jwv.y;
    float2 bdv = g_bd[n];
    float2 vn = h2_to_f2(__ldg(&X[n * HC + lane]));
    float4 b;
    b.x = wnx * sx + bdv.x * vn.x;
    b.y = wny * sx + bdv.y * vn.x;
    b.z = wnx * sy + bdv.x * vn.y;
    b.w = wny * sy + bdv.y * vn.y;
    int idx = n * HC + lane;
    g_BJ[idx] = f4_to_h4(b);
    float4 z;                              // z0 = jw * b
    z.x = jwv.x * b.x - jwv.y * b.y;
    z.y = jwv.x * b.y + jwv.y * b.x;
    z.z = jwv.x * b.z - jwv.y * b.w;
    z.w = jwv.x * b.w + jwv.y * b.z;
    g_Z0[idx] = f4_to_h4(z);
    float c0v = __ldg(&c0[l]);
    g_OUT[idx] = make_float2(c0v * vn.x, c0v * vn.y);
}

// ---------------- b_j from COMPLEX fp16 input (j>0): reads Y16 -------------
__global__ void k_bj_cplx() {
    int warp = (blockIdx.x * blockDim.x + threadIdx.x) >> 5;
    int lane = threadIdx.x & 31;
    if (warp >= NN) return;
    int n = g_ordR[warp];
    int p = g_rptr[n], end = g_rptr[n + 1];
    float4 a = make_float4(0.f, 0.f, 0.f, 0.f);
    for (; p + 8 <= end; p += 8) {
        int d0 = __ldg(&g_adjR[p + 0]), d1 = __ldg(&g_adjR[p + 1]);
        int d2 = __ldg(&g_adjR[p + 2]), d3 = __ldg(&g_adjR[p + 3]);
        int d4 = __ldg(&g_adjR[p + 4]), d5 = __ldg(&g_adjR[p + 5]);
        int d6 = __ldg(&g_adjR[p + 6]), d7 = __ldg(&g_adjR[p + 7]);
        float4 v0 = h4_to_f4(__ldg(&g_Y16[d0 * HC + lane]));
        float4 v1 = h4_to_f4(__ldg(&g_Y16[d1 * HC + lane]));
        float4 v2 = h4_to_f4(__ldg(&g_Y16[d2 * HC + lane]));
        float4 v3 = h4_to_f4(__ldg(&g_Y16[d3 * HC + lane]));
        float4 v4 = h4_to_f4(__ldg(&g_Y16[d4 * HC + lane]));
        float4 v5 = h4_to_f4(__ldg(&g_Y16[d5 * HC + lane]));
        float4 v6 = h4_to_f4(__ldg(&g_Y16[d6 * HC + lane]));
        float4 v7 = h4_to_f4(__ldg(&g_Y16[d7 * HC + lane]));
        a.x += v0.x + v1.x + v2.x + v3.x + v4.x + v5.x + v6.x + v7.x;
        a.y += v0.y + v1.y + v2.y + v3.y + v4.y + v5.y + v6.y + v7.y;
        a.z += v0.z + v1.z + v2.z + v3.z + v4.z + v5.z + v6.z + v7.z;
        a.w += v0.w + v1.w + v2.w + v3.w + v4.w + v5.w + v6.w + v7.w;
    }
    for (; p < end; ++p) {
        int d = __ldg(&g_adjR[p]);
        float4 v = h4_to_f4(__ldg(&g_Y16[d * HC + lane]));
        a.x += v.x; a.y += v.y; a.z += v.z; a.w += v.w;
    }
    float2 jwv = g_jw[n];
    float wnx = -jwv.x, wny = -jwv.y;
    float2 bdv = g_bd[n];
    int idx = n * HC + lane;
    float4 vn = h4_to_f4(g_Y16[idx]);
    float4 b;
    b.x = wnx * a.x - wny * a.y + bdv.x * vn.x - bdv.y * vn.y;
    b.y = wnx * a.y + wny * a.x + bdv.x * vn.y + bdv.y * vn.x;
    b.z = wnx * a.z - wny * a.w + bdv.x * vn.z - bdv.y * vn.w;
    b.w = wnx * a.w + wny * a.z + bdv.x * vn.w + bdv.y * vn.z;
    g_BJ[idx] = f4_to_h4(b);
    float4 z;
    z.x = jwv.x * b.x - jwv.y * b.y;
    z.y = jwv.x * b.y + jwv.y * b.x;
    z.z = jwv.x * b.z - jwv.y * b.w;
    z.w = jwv.x * b.w + jwv.y * b.z;
    g_Z0[idx] = f4_to_h4(z);
}

// ---------------- jacobi: y[n] = sum_{e:col=n} z[src] + b_j[n] -------------
// FINAL=false: write z_out = jw*y.
// FINAL,!LAST: write Y16=y, OUT += 2*Re(cj*y).
// FINAL,LAST : o = OUT + 2*Re(cj*y); XR = relu(o) fp16; SCORES: also g_S.
template <bool FINAL, bool LAST, bool SCORES>
__global__ void k_jac(int in_sel, int out_sel, const float* __restrict__ cj, int cjoff,
                      const float* __restrict__ tw) {
    int warp = (blockIdx.x * blockDim.x + threadIdx.x) >> 5;
    int lane = threadIdx.x & 31;
    if (warp >= NN) return;
    int n = g_ordC[warp];
    const uint2* __restrict__ Zin = zbuf(in_sel);
    int p = g_cptr[n], end = g_cptr[n + 1];
    float4 acc = make_float4(0.f, 0.f, 0.f, 0.f);
    for (; p + 8 <= end; p += 8) {
        int s0 = __ldg(&g_adjC[p + 0]), s1 = __ldg(&g_adjC[p + 1]);
        int s2 = __ldg(&g_adjC[p + 2]), s3 = __ldg(&g_adjC[p + 3]);
        int s4 = __ldg(&g_adjC[p + 4]), s5 = __ldg(&g_adjC[p + 5]);
        int s6 = __ldg(&g_adjC[p + 6]), s7 = __ldg(&g_adjC[p + 7]);
        float4 v0 = h4_to_f4(__ldg(&Zin[s0 * HC + lane]));
        float4 v1 = h4_to_f4(__ldg(&Zin[s1 * HC + lane]));
        float4 v2 = h4_to_f4(__ldg(&Zin[s2 * HC + lane]));
        float4 v3 = h4_to_f4(__ldg(&Zin[s3 * HC + lane]));
        float4 v4 = h4_to_f4(__ldg(&Zin[s4 * HC + lane]));
        float4 v5 = h4_to_f4(__ldg(&Zin[s5 * HC + lane]));
        float4 v6 = h4_to_f4(__ldg(&Zin[s6 * HC + lane]));
        float4 v7 = h4_to_f4(__ldg(&Zin[s7 * HC + lane]));
        acc.x += v0.x + v1.x + v2.x + v3.x + v4.x + v5.x + v6.x + v7.x;
        acc.y += v0.y + v1.y + v2.y + v3.y + v4.y + v5.y + v6.y + v7.y;
        acc.z += v0.z + v1.z + v2.z + v3.z + v4.z + v5.z + v6.z + v7.z;
        acc.w += v0.w + v1.w + v2.w + v3.w + v4.w + v5.w + v6.w + v7.w;
    }
    for (; p < end; ++p) {
        int s = __ldg(&g_adjC[p]);
        float4 v = h4_to_f4(__ldg(&Zin[s * HC + lane]));
        acc.x += v.x; acc.y += v.y; acc.z += v.z; acc.w += v.w;
    }
    int idx = n * HC + lane;
    float4 b = h4_to_f4(g_BJ[idx]);
    acc.x += b.x; acc.y += b.y; acc.z += b.z; acc.w += b.w;   // acc = y
    if (!FINAL) {
        float2 jwv = g_jw[n];
        float4 z;
        z.x = jwv.x * acc.x - jwv.y * acc.y;
        z.y = jwv.x * acc.y + jwv.y * acc.x;
        z.z = jwv.x * acc.z - jwv.y * acc.w;
        z.w = jwv.x * acc.w + jwv.y * acc.z;
        zbuf(out_sel)[idx] = f4_to_h4(z);
    } else {
        float cr = __ldg(&cj[cjoff]), ci = __ldg(&cj[cjoff + 1]);
        float2 o = g_OUT[idx];
        o.x += 2.0f * (cr * acc.x - ci * acc.y);
        o.y += 2.0f * (cr * acc.z - ci * acc.w);
        if (!LAST) {
            g_Y16[idx] = f4_to_h4(acc);
            g_OUT[idx] = o;
        } else {
            float2 xr = make_float2(fmaxf(o.x, 0.f), fmaxf(o.y, 0.f));
            g_XR[idx] = f2_to_h2(xr);
            if (SCORES) {
                float2 wv = __ldg(&((const float2*)tw)[lane]);
                float dot = xr.x * wv.x + xr.y * wv.y;
                float nsq = wv.x * wv.x + wv.y * wv.y;
                for (int off = 16; off > 0; off >>= 1) {
                    dot += __shfl_xor_sync(0xFFFFFFFFu, dot, off);
                    nsq += __shfl_xor_sync(0xFFFFFFFFu, nsq, off);
                }
                if (lane == 0) g_S[n] = tanhf(dot * rsqrtf(nsq));
            }
        }
    }
}

__device__ __forceinline__ unsigned long long make_key(float f, int idx) {
    unsigned u = __float_as_uint(f);
    u = (u & 0x80000000u) ? ~u : (u | 0x80000000u);
    return ((unsigned long long)u << 32) | (unsigned)(0xFFFFFFFFu - (unsigned)idx);
}

// ---------------- per-graph exact k-th largest key via byte radix-select ---
__global__ void k_select() {
    __shared__ int hist[256];
    __shared__ unsigned long long s_prefix;
    __shared__ int s_kk;
    int g = blockIdx.x;
    if (threadIdx.x == 0) { s_prefix = 0ULL; s_kk = KKEEP; }
    __syncthreads();
    for (int pass = 7; pass >= 0; --pass) {
        int shift = pass * 8;
        hist[threadIdx.x] = 0;
        __syncthreads();
        unsigned long long pfx = s_prefix;
        unsigned long long maskhi = (pass == 7) ? 0ULL : ((~0ULL) << (shift + 8));
        for (int i = threadIdx.x; i < NPG; i += 256) {
            unsigned long long key = make_key(g_S[g * NPG + i], i);
            if ((key & maskhi) == (pfx & maskhi))
                atomicAdd(&hist[(int)((key >> shift) & 0xFF)], 1);
        }
        __syncthreads();
        if (threadIdx.x == 0) {
            int kk = s_kk;
            int b = 255;
            for (;;) {
                int c = hist[b];
                if (c >= kk) break;
                kk -= c;
                --b;
            }
            s_kk = kk;
            s_prefix = pfx | ((unsigned long long)b << shift);
        }
        __syncthreads();
    }
    if (threadIdx.x == 0) g_thr[g] = s_prefix;
}

// ---------------- masked mean pool -----------------------------------------
__global__ void k_pool() {
    __shared__ float sm[256];
    int g = blockIdx.x;
    int ch = threadIdx.x & 63;
    int nl = threadIdx.x >> 6;
    unsigned long long thr = g_thr[g];
    float acc = 0.f;
    for (int i = nl; i < NPG; i += 4) {
        int node = g * NPG + i;
        float sv = g_S[node];
        if (make_key(sv, i) >= thr) {
            float2 f = h2_to_f2(g_XR[node * HC + (ch >> 1)]);
            acc += ((ch & 1) ? f.y : f.x) * sv;
        }
    }
    sm[threadIdx.x] = acc;
    __syncthreads();
    if (nl == 0) {
        float t = sm[ch] + sm[64 + ch] + sm[128 + ch] + sm[192 + ch];
        g_pool[g * HH + ch] = t * (1.0f / (float)KKEEP);
    }
}

// ---------------- final linear ---------------------------------------------
__global__ void k_linear(const float* __restrict__ lw, const float* __restrict__ lb,
                         float* __restrict__ out) {
    int t = threadIdx.x;
    if (t >= GG * 10) return;
    int g = t / 10, o = t % 10;
    float acc = lb[o];
    #pragma unroll
    for (int h = 0; h < HH; ++h)
        acc += g_pool[g * HH + h] * lw[h * 10 + o];
    out[g * 10 + o] = acc;
}

// ---------------------------------------------------------------------------
extern "C" void kernel_launch(void* const* d_in, const int* in_sizes, int n_in,
                              void* d_out, int out_size) {
    const float* x     = (const float*)d_in[0];
    const int*   ei    = (const int*)d_in[1];
    const float* h     = (const float*)d_in[3];
    const float* alpha = (const float*)d_in[4];
    const float* c0    = (const float*)d_in[5];
    const float* cj    = (const float*)d_in[6];
    const float* tw    = (const float*)d_in[7];
    const float* lw    = (const float*)d_in[8];
    const float* lb    = (const float*)d_in[9];
    float* out = (float*)d_out;

    const int SPMM_GRID = (NN * 32 + 255) / 256;

    // CSR build (both directions) + degree sort
    k_zero<<<196, 256>>>();
    k_hist<<<1024, 256>>>(ei);
    k_scan<<<2, 1024>>>();
    k_fill<<<1024, 256>>>(ei);
    k_deg_hist<<<196, 256>>>();
    k_deg_scan<<<2, DB>>>();
    k_deg_fill<<<196, 256>>>();
    k_x2h<<<1024, 256>>>(x);

    for (int l = 0; l < 2; ++l) {
        k_params<<<(NN + 255) / 256, 256>>>(h, alpha, l);
        for (int j = 0; j < 3; ++j) {
            if (j == 0)
                k_bj_real<<<SPMM_GRID, 256>>>(l, c0, l);
            else
                k_bj_cplx<<<SPMM_GRID, 256>>>();
            int cjoff = (l * 3 + j) * 2;
            k_jac<false, false, false><<<SPMM_GRID, 256>>>(0, 1, cj, cjoff, tw);
            k_jac<false, false, false><<<SPMM_GRID, 256>>>(1, 0, cj, cjoff, tw);
            k_jac<false, false, false><<<SPMM_GRID, 256>>>(0, 1, cj, cjoff, tw);
            if (j < 2)
                k_jac<true, false, false><<<SPMM_GRID, 256>>>(1, 0, cj, cjoff, tw);
            else if (l == 0)
                k_jac<true, true, false><<<SPMM_GRID, 256>>>(1, 0, cj, cjoff, tw);
            else
                k_jac<true, true, true><<<SPMM_GRID, 256>>>(1, 0, cj, cjoff, tw);
        }
    }

    k_select<<<GG, 256>>>();
    k_pool<<<GG, 256>>>();
    k_linear<<<1, 128>>>(lw, lb, out);
}

// round 5
// speedup vs baseline: 1.5546x; 1.0236x over previous
#include <cuda_runtime.h>
#include <cuda_fp16.h>

// ---------------------------------------------------------------------------
// CayleyNet: 2x CayleyConv (R=3, K=4 Jacobi) + TopKPooling(0.9) + mean pool + linear
// fp16 storage (z, y, BJ, x), fp32 accumulation, jw-folded Jacobi,
// fused relu/scores epilogues, identity scheduling, uint16 adjacency.
// ---------------------------------------------------------------------------

#define NN    50000
#define EE    800000
#define HH    64
#define HC    32          // lanes per node: lane = 2 complex channels
#define GG    10
#define NPG   5000
#define KKEEP 4500        // ceil(0.9 * 5000)

// ---------------- static device scratch (no allocations allowed) ----------
__device__ int g_cntR[NN];
__device__ int g_cntC[NN];
__device__ int g_rptr[NN + 1];
__device__ int g_cptr[NN + 1];
__device__ unsigned short g_adjR[EE];  // grouped by row: stores col (dst), ids < 65536
__device__ unsigned short g_adjC[EE];  // grouped by col: stores row (src)
__device__ float2 g_jw[NN];            // h * tmp_left[n]
__device__ float2 g_bd[NN];            // b_dia[n]
__device__ uint2  g_BJ[NN * HC];       // b_j (fp16 x4)
__device__ uint2  g_Z0[NN * HC];       // z = jw*y (fp16 x4) ping
__device__ uint2  g_Z1[NN * HC];       // z pong
__device__ uint2  g_Y16[NN * HC];      // final y per order (fp16 x4)
__device__ float2 g_OUT[NN * HC];      // real accumulator (fp32, 2 ch)
__device__ unsigned g_XH[NN * HC];     // fp16 copy of input x (packed half2)
__device__ unsigned g_XR[NN * HC];     // relu'd features (packed half2)
__device__ float  g_S[NN];             // topk scores
__device__ unsigned long long g_thr[GG];
__device__ float g_pool[GG * HH];

__device__ __forceinline__ uint2* zbuf(int s) { return s ? g_Z1 : g_Z0; }

// register-friendly reinterpret helpers
union H4U { uint2 u; __half2 h[2]; };
union H2U { unsigned u; __half2 h; };

__device__ __forceinline__ float4 h4_to_f4(uint2 v) {
    H4U c; c.u = v;
    float2 fa = __half22float2(c.h[0]);
    float2 fb = __half22float2(c.h[1]);
    return make_float4(fa.x, fa.y, fb.x, fb.y);
}
__device__ __forceinline__ uint2 f4_to_h4(float4 f) {
    H4U c;
    c.h[0] = __float22half2_rn(make_float2(f.x, f.y));
    c.h[1] = __float22half2_rn(make_float2(f.z, f.w));
    return c.u;
}
__device__ __forceinline__ float2 h2_to_f2(unsigned v) {
    H2U c; c.u = v;
    return __half22float2(c.h);
}
__device__ __forceinline__ unsigned f2_to_h2(float2 f) {
    H2U c; c.h = __float22half2_rn(f);
    return c.u;
}

// ---------------- CSR construction ----------------------------------------
__global__ void k_zero() {
    for (int i = blockIdx.x * blockDim.x + threadIdx.x; i < NN; i += gridDim.x * blockDim.x) {
        g_cntR[i] = 0;
        g_cntC[i] = 0;
    }
}

__global__ void k_hist(const int* __restrict__ ei) {
    for (int e = blockIdx.x * blockDim.x + threadIdx.x; e < EE; e += gridDim.x * blockDim.x) {
        atomicAdd(&g_cntR[ei[e]], 1);
        atomicAdd(&g_cntC[ei[EE + e]], 1);
    }
}

// 2 blocks: block 0 scans cntR->rptr, block 1 scans cntC->cptr.
// Also rewrites cnt[i] = start offset (fill cursor).
__global__ void k_scan() {
    __shared__ int sm[1024];
    const int PER = 49;
    int which = blockIdx.x;
    int* cnt = which ? g_cntC : g_cntR;
    int* ptr = which ? g_cptr : g_rptr;
    int t = threadIdx.x;
    int base = t * PER;
    int local = 0;
    for (int i = 0; i < PER; ++i) {
        int idx = base + i;
        if (idx < NN) local += cnt[idx];
    }
    sm[t] = local;
    __syncthreads();
    for (int off = 1; off < 1024; off <<= 1) {
        int v = (t >= off) ? sm[t - off] : 0;
        __syncthreads();
        sm[t] += v;
        __syncthreads();
    }
    int run = sm[t] - local;
    for (int i = 0; i < PER; ++i) {
        int idx = base + i;
        if (idx < NN) {
            int c = cnt[idx];
            ptr[idx] = run;
            cnt[idx] = run;     // cursor for k_fill
            run += c;
        }
    }
    if (t == 1023) ptr[NN] = sm[1023];
}

__global__ void k_fill(const int* __restrict__ ei) {
    for (int e = blockIdx.x * blockDim.x + threadIdx.x; e < EE; e += gridDim.x * blockDim.x) {
        int r = ei[e];
        int c = ei[EE + e];
        g_adjR[atomicAdd(&g_cntR[r], 1)] = (unsigned short)c;
        g_adjC[atomicAdd(&g_cntC[c], 1)] = (unsigned short)r;
    }
}

// ---------------- x -> fp16 copy -------------------------------------------
__global__ void k_x2h(const float* __restrict__ x) {
    for (int i = blockIdx.x * blockDim.x + threadIdx.x; i < NN * HC; i += gridDim.x * blockDim.x) {
        float2 v = ((const float2*)x)[i];
        g_XH[i] = f2_to_h2(v);
    }
}

// ---------------- per-layer node parameters --------------------------------
__global__ void k_params(const float* __restrict__ h, const float* __restrict__ alpha, int l) {
    float hv = h[l], av = alpha[l];
    for (int n = blockIdx.x * blockDim.x + threadIdx.x; n < NN; n += gridDim.x * blockDim.x) {
        float deg = (float)(g_rptr[n + 1] - g_rptr[n]);
        float a = hv * (deg - av);
        float inv = 1.0f / (a * a + 1.0f);
        g_jw[n] = make_float2(hv * a * inv, -hv * inv);
        g_bd[n] = make_float2((a * a - 1.0f) * inv, -2.0f * a * inv);
    }
}

// ---------------- b_j from REAL fp16 input (j==0): also init OUT, Z0 -------
__global__ void k_bj_real(int use_xr, const float* __restrict__ c0, int l) {
    int warp = (blockIdx.x * blockDim.x + threadIdx.x) >> 5;
    int lane = threadIdx.x & 31;
    if (warp >= NN) return;
    int n = warp;
    const unsigned* __restrict__ X = use_xr ? g_XR : g_XH;
    int p = g_rptr[n], end = g_rptr[n + 1];
    float sx = 0.f, sy = 0.f;
    for (; p + 8 <= end; p += 8) {
        int d0 = __ldg(&g_adjR[p + 0]), d1 = __ldg(&g_adjR[p + 1]);
        int d2 = __ldg(&g_adjR[p + 2]), d3 = __ldg(&g_adjR[p + 3]);
        int d4 = __ldg(&g_adjR[p + 4]), d5 = __ldg(&g_adjR[p + 5]);
        int d6 = __ldg(&g_adjR[p + 6]), d7 = __ldg(&g_adjR[p + 7]);
        float2 f0 = h2_to_f2(__ldg(&X[d0 * HC + lane]));
        float2 f1 = h2_to_f2(__ldg(&X[d1 * HC + lane]));
        float2 f2 = h2_to_f2(__ldg(&X[d2 * HC + lane]));
        float2 f3 = h2_to_f2(__ldg(&X[d3 * HC + lane]));
        float2 f4 = h2_to_f2(__ldg(&X[d4 * HC + lane]));
        float2 f5 = h2_to_f2(__ldg(&X[d5 * HC + lane]));
        float2 f6 = h2_to_f2(__ldg(&X[d6 * HC + lane]));
        float2 f7 = h2_to_f2(__ldg(&X[d7 * HC + lane]));
        sx += f0.x + f1.x + f2.x + f3.x + f4.x + f5.x + f6.x + f7.x;
        sy += f0.y + f1.y + f2.y + f3.y + f4.y + f5.y + f6.y + f7.y;
    }
    for (; p < end; ++p) {
        int d = __ldg(&g_adjR[p]);
        float2 f = h2_to_f2(__ldg(&X[d * HC + lane]));
        sx += f.x;
        sy += f.y;
    }
    float2 jwv = g_jw[n];
    float wnx = -jwv.x, wny = -jwv.y;
    float2 bdv = g_bd[n];
    float2 vn = h2_to_f2(__ldg(&X[n * HC + lane]));
    float4 b;
    b.x = wnx * sx + bdv.x * vn.x;
    b.y = wny * sx + bdv.y * vn.x;
    b.z = wnx * sy + bdv.x * vn.y;
    b.w = wny * sy + bdv.y * vn.y;
    int idx = n * HC + lane;
    g_BJ[idx] = f4_to_h4(b);
    float4 z;                              // z0 = jw * b
    z.x = jwv.x * b.x - jwv.y * b.y;
    z.y = jwv.x * b.y + jwv.y * b.x;
    z.z = jwv.x * b.z - jwv.y * b.w;
    z.w = jwv.x * b.w + jwv.y * b.z;
    g_Z0[idx] = f4_to_h4(z);
    float c0v = __ldg(&c0[l]);
    g_OUT[idx] = make_float2(c0v * vn.x, c0v * vn.y);
}

// ---------------- b_j from COMPLEX fp16 input (j>0): reads Y16 -------------
__global__ void k_bj_cplx() {
    int warp = (blockIdx.x * blockDim.x + threadIdx.x) >> 5;
    int lane = threadIdx.x & 31;
    if (warp >= NN) return;
    int n = warp;
    int p = g_rptr[n], end = g_rptr[n + 1];
    float4 a = make_float4(0.f, 0.f, 0.f, 0.f);
    for (; p + 8 <= end; p += 8) {
        int d0 = __ldg(&g_adjR[p + 0]), d1 = __ldg(&g_adjR[p + 1]);
        int d2 = __ldg(&g_adjR[p + 2]), d3 = __ldg(&g_adjR[p + 3]);
        int d4 = __ldg(&g_adjR[p + 4]), d5 = __ldg(&g_adjR[p + 5]);
        int d6 = __ldg(&g_adjR[p + 6]), d7 = __ldg(&g_adjR[p + 7]);
        float4 v0 = h4_to_f4(__ldg(&g_Y16[d0 * HC + lane]));
        float4 v1 = h4_to_f4(__ldg(&g_Y16[d1 * HC + lane]));
        float4 v2 = h4_to_f4(__ldg(&g_Y16[d2 * HC + lane]));
        float4 v3 = h4_to_f4(__ldg(&g_Y16[d3 * HC + lane]));
        float4 v4 = h4_to_f4(__ldg(&g_Y16[d4 * HC + lane]));
        float4 v5 = h4_to_f4(__ldg(&g_Y16[d5 * HC + lane]));
        float4 v6 = h4_to_f4(__ldg(&g_Y16[d6 * HC + lane]));
        float4 v7 = h4_to_f4(__ldg(&g_Y16[d7 * HC + lane]));
        a.x += v0.x + v1.x + v2.x + v3.x + v4.x + v5.x + v6.x + v7.x;
        a.y += v0.y + v1.y + v2.y + v3.y + v4.y + v5.y + v6.y + v7.y;
        a.z += v0.z + v1.z + v2.z + v3.z + v4.z + v5.z + v6.z + v7.z;
        a.w += v0.w + v1.w + v2.w + v3.w + v4.w + v5.w + v6.w + v7.w;
    }
    for (; p < end; ++p) {
        int d = __ldg(&g_adjR[p]);
        float4 v = h4_to_f4(__ldg(&g_Y16[d * HC + lane]));
        a.x += v.x; a.y += v.y; a.z += v.z; a.w += v.w;
    }
    float2 jwv = g_jw[n];
    float wnx = -jwv.x, wny = -jwv.y;
    float2 bdv = g_bd[n];
    int idx = n * HC + lane;
    float4 vn = h4_to_f4(g_Y16[idx]);
    float4 b;
    b.x = wnx * a.x - wny * a.y + bdv.x * vn.x - bdv.y * vn.y;
    b.y = wnx * a.y + wny * a.x + bdv.x * vn.y + bdv.y * vn.x;
    b.z = wnx * a.z - wny * a.w + bdv.x * vn.z - bdv.y * vn.w;
    b.w = wnx * a.w + wny * a.z + bdv.x * vn.w + bdv.y * vn.z;
    g_BJ[idx] = f4_to_h4(b);
    float4 z;
    z.x = jwv.x * b.x - jwv.y * b.y;
    z.y = jwv.x * b.y + jwv.y * b.x;
    z.z = jwv.x * b.z - jwv.y * b.w;
    z.w = jwv.x * b.w + jwv.y * b.z;
    g_Z0[idx] = f4_to_h4(z);
}

// ---------------- jacobi: y[n] = sum_{e:col=n} z[src] + b_j[n] -------------
// FINAL=false: write z_out = jw*y.
// FINAL,!LAST: write Y16=y, OUT += 2*Re(cj*y).
// FINAL,LAST : o = OUT + 2*Re(cj*y); XR = relu(o) fp16; SCORES: also g_S.
template <bool FINAL, bool LAST, bool SCORES>
__global__ void k_jac(int in_sel, int out_sel, const float* __restrict__ cj, int cjoff,
                      const float* __restrict__ tw) {
    int warp = (blockIdx.x * blockDim.x + threadIdx.x) >> 5;
    int lane = threadIdx.x & 31;
    if (warp >= NN) return;
    int n = warp;
    const uint2* __restrict__ Zin = zbuf(in_sel);
    int p = g_cptr[n], end = g_cptr[n + 1];
    float4 acc = make_float4(0.f, 0.f, 0.f, 0.f);
    for (; p + 8 <= end; p += 8) {
        int s0 = __ldg(&g_adjC[p + 0]), s1 = __ldg(&g_adjC[p + 1]);
        int s2 = __ldg(&g_adjC[p + 2]), s3 = __ldg(&g_adjC[p + 3]);
        int s4 = __ldg(&g_adjC[p + 4]), s5 = __ldg(&g_adjC[p + 5]);
        int s6 = __ldg(&g_adjC[p + 6]), s7 = __ldg(&g_adjC[p + 7]);
        float4 v0 = h4_to_f4(__ldg(&Zin[s0 * HC + lane]));
        float4 v1 = h4_to_f4(__ldg(&Zin[s1 * HC + lane]));
        float4 v2 = h4_to_f4(__ldg(&Zin[s2 * HC + lane]));
        float4 v3 = h4_to_f4(__ldg(&Zin[s3 * HC + lane]));
        float4 v4 = h4_to_f4(__ldg(&Zin[s4 * HC + lane]));
        float4 v5 = h4_to_f4(__ldg(&Zin[s5 * HC + lane]));
        float4 v6 = h4_to_f4(__ldg(&Zin[s6 * HC + lane]));
        float4 v7 = h4_to_f4(__ldg(&Zin[s7 * HC + lane]));
        acc.x += v0.x + v1.x + v2.x + v3.x + v4.x + v5.x + v6.x + v7.x;
        acc.y += v0.y + v1.y + v2.y + v3.y + v4.y + v5.y + v6.y + v7.y;
        acc.z += v0.z + v1.z + v2.z + v3.z + v4.z + v5.z + v6.z + v7.z;
        acc.w += v0.w + v1.w + v2.w + v3.w + v4.w + v5.w + v6.w + v7.w;
    }
    for (; p < end; ++p) {
        int s = __ldg(&g_adjC[p]);
        float4 v = h4_to_f4(__ldg(&Zin[s * HC + lane]));
        acc.x += v.x; acc.y += v.y; acc.z += v.z; acc.w += v.w;
    }
    int idx = n * HC + lane;
    float4 b = h4_to_f4(g_BJ[idx]);
    acc.x += b.x; acc.y += b.y; acc.z += b.z; acc.w += b.w;   // acc = y
    if (!FINAL) {
        float2 jwv = g_jw[n];
        float4 z;
        z.x = jwv.x * acc.x - jwv.y * acc.y;
        z.y = jwv.x * acc.y + jwv.y * acc.x;
        z.z = jwv.x * acc.z - jwv.y * acc.w;
        z.w = jwv.x * acc.w + jwv.y * acc.z;
        zbuf(out_sel)[idx] = f4_to_h4(z);
    } else {
        float cr = __ldg(&cj[cjoff]), ci = __ldg(&cj[cjoff + 1]);
        float2 o = g_OUT[idx];
        o.x += 2.0f * (cr * acc.x - ci * acc.y);
        o.y += 2.0f * (cr * acc.z - ci * acc.w);
        if (!LAST) {
            g_Y16[idx] = f4_to_h4(acc);
            g_OUT[idx] = o;
        } else {
            float2 xr = make_float2(fmaxf(o.x, 0.f), fmaxf(o.y, 0.f));
            g_XR[idx] = f2_to_h2(xr);
            if (SCORES) {
                float2 wv = __ldg(&((const float2*)tw)[lane]);
                float dot = xr.x * wv.x + xr.y * wv.y;
                float nsq = wv.x * wv.x + wv.y * wv.y;
                for (int off = 16; off > 0; off >>= 1) {
                    dot += __shfl_xor_sync(0xFFFFFFFFu, dot, off);
                    nsq += __shfl_xor_sync(0xFFFFFFFFu, nsq, off);
                }
                if (lane == 0) g_S[n] = tanhf(dot * rsqrtf(nsq));
            }
        }
    }
}

__device__ __forceinline__ unsigned long long make_key(float f, int idx) {
    unsigned u = __float_as_uint(f);
    u = (u & 0x80000000u) ? ~u : (u | 0x80000000u);
    return ((unsigned long long)u << 32) | (unsigned)(0xFFFFFFFFu - (unsigned)idx);
}

// ---------------- per-graph exact k-th largest key via byte radix-select ---
__global__ void k_select() {
    __shared__ int hist[256];
    __shared__ unsigned long long s_prefix;
    __shared__ int s_kk;
    int g = blockIdx.x;
    if (threadIdx.x == 0) { s_prefix = 0ULL; s_kk = KKEEP; }
    __syncthreads();
    for (int pass = 7; pass >= 0; --pass) {
        int shift = pass * 8;
        hist[threadIdx.x] = 0;
        __syncthreads();
        unsigned long long pfx = s_prefix;
        unsigned long long maskhi = (pass == 7) ? 0ULL : ((~0ULL) << (shift + 8));
        for (int i = threadIdx.x; i < NPG; i += 256) {
            unsigned long long key = make_key(g_S[g * NPG + i], i);
            if ((key & maskhi) == (pfx & maskhi))
                atomicAdd(&hist[(int)((key >> shift) & 0xFF)], 1);
        }
        __syncthreads();
        if (threadIdx.x == 0) {
            int kk = s_kk;
            int b = 255;
            for (;;) {
                int c = hist[b];
                if (c >= kk) break;
                kk -= c;
                --b;
            }
            s_kk = kk;
            s_prefix = pfx | ((unsigned long long)b << shift);
        }
        __syncthreads();
    }
    if (threadIdx.x == 0) g_thr[g] = s_prefix;
}

// ---------------- masked mean pool -----------------------------------------
__global__ void k_pool() {
    __shared__ float sm[256];
    int g = blockIdx.x;
    int ch = threadIdx.x & 63;
    int nl = threadIdx.x >> 6;
    unsigned long long thr = g_thr[g];
    float acc = 0.f;
    for (int i = nl; i < NPG; i += 4) {
        int node = g * NPG + i;
        float sv = g_S[node];
        if (make_key(sv, i) >= thr) {
            float2 f = h2_to_f2(g_XR[node * HC + (ch >> 1)]);
            acc += ((ch & 1) ? f.y : f.x) * sv;
        }
    }
    sm[threadIdx.x] = acc;
    __syncthreads();
    if (nl == 0) {
        float t = sm[ch] + sm[64 + ch] + sm[128 + ch] + sm[192 + ch];
        g_pool[g * HH + ch] = t * (1.0f / (float)KKEEP);
    }
}

// ---------------- final linear ---------------------------------------------
__global__ void k_linear(const float* __restrict__ lw, const float* __restrict__ lb,
                         float* __restrict__ out) {
    int t = threadIdx.x;
    if (t >= GG * 10) return;
    int g = t / 10, o = t % 10;
    float acc = lb[o];
    #pragma unroll
    for (int h = 0; h < HH; ++h)
        acc += g_pool[g * HH + h] * lw[h * 10 + o];
    out[g * 10 + o] = acc;
}

// ---------------------------------------------------------------------------
extern "C" void kernel_launch(void* const* d_in, const int* in_sizes, int n_in,
                              void* d_out, int out_size) {
    const float* x     = (const float*)d_in[0];
    const int*   ei    = (const int*)d_in[1];
    const float* h     = (const float*)d_in[3];
    const float* alpha = (const float*)d_in[4];
    const float* c0    = (const float*)d_in[5];
    const float* cj    = (const float*)d_in[6];
    const float* tw    = (const float*)d_in[7];
    const float* lw    = (const float*)d_in[8];
    const float* lb    = (const float*)d_in[9];
    float* out = (float*)d_out;

    const int SPMM_GRID = (NN * 32 + 255) / 256;

    // CSR build (both directions)
    k_zero<<<196, 256>>>();
    k_hist<<<1024, 256>>>(ei);
    k_scan<<<2, 1024>>>();
    k_fill<<<1024, 256>>>(ei);
    k_x2h<<<1024, 256>>>(x);

    for (int l = 0; l < 2; ++l) {
        k_params<<<(NN + 255) / 256, 256>>>(h, alpha, l);
        for (int j = 0; j < 3; ++j) {
            if (j == 0)
                k_bj_real<<<SPMM_GRID, 256>>>(l, c0, l);
            else
                k_bj_cplx<<<SPMM_GRID, 256>>>();
            int cjoff = (l * 3 + j) * 2;
            k_jac<false, false, false><<<SPMM_GRID, 256>>>(0, 1, cj, cjoff, tw);
            k_jac<false, false, false><<<SPMM_GRID, 256>>>(1, 0, cj, cjoff, tw);
            k_jac<false, false, false><<<SPMM_GRID, 256>>>(0, 1, cj, cjoff, tw);
            if (j < 2)
                k_jac<true, false, false><<<SPMM_GRID, 256>>>(1, 0, cj, cjoff, tw);
            else if (l == 0)
                k_jac<true, true, false><<<SPMM_GRID, 256>>>(1, 0, cj, cjoff, tw);
            else
                k_jac<true, true, true><<<SPMM_GRID, 256>>>(1, 0, cj, cjoff, tw);
        }
    }

    k_select<<<GG, 256>>>();
    k_pool<<<GG, 256>>>();
    k_linear<<<1, 128>>>(lw, lb, out);
}